// round 6
// baseline (speedup 1.0000x reference)
#include <cuda_runtime.h>

#define EPSF     1e-9f
#define BCE_EPSF 1e-7f
#define NGT      150
#define NGT_PAD  152
#define NBLOCKS  1008   // 256 anchors per block (128 threads x 2 anchors)

__device__ double       g_acc;
__device__ unsigned int g_count;

struct AnchorState {
    float brx, bry, ntlx, ntly;   // anchor corners, tl negated
    float giou, fb, gcf, thresh;  // thresh = area1 * (2/3)
};

static __device__ __forceinline__ AnchorState prep_anchor(const float* __restrict__ p,
                                                          const float* __restrict__ q) {
    float ox = p[0], oy = p[1], ow = p[2], oh = p[3], oc = p[4];
    float gx = q[0], gy = q[1], gw = q[2], gh = q[3], gcf = q[4];

    float tl1x = ox - 0.5f * ow, tl1y = oy - 0.5f * oh;
    float br1x = ox + 0.5f * ow, br1y = oy + 0.5f * oh;
    float area1 = ow * oh;

    // ---- DIoU vs paired gt ----
    float tl2x = gx - 0.5f * gw, tl2y = gy - 0.5f * gh;
    float br2x = gx + 0.5f * gw, br2y = gy + 0.5f * gh;
    float area2 = gw * gh;

    float iwx = fmaxf(fminf(br1x, br2x) - fmaxf(tl1x, tl2x), 0.0f);
    float iwy = fmaxf(fminf(br1y, br2y) - fmaxf(tl1y, tl2y), 0.0f);
    float inter = iwx * iwy;
    float iou = inter / (area1 + area2 - inter + EPSF);

    float dx = ox - gx, dy = oy - gy;
    float cd2 = dx * dx + dy * dy;
    float ex = fmaxf(br1x, br2x) - fminf(tl1x, tl2x);
    float ey = fmaxf(br1y, br2y) - fminf(tl1y, tl2y);
    float diou = iou - cd2 / (ex * ex + ey * ey + EPSF);

    // ---- focal BCE pieces (background-independent) ----
    float pcl = fminf(fmaxf(oc, BCE_EPSF), 1.0f - BCE_EPSF);
    float bce = -(gcf * __logf(pcl) + (1.0f - gcf) * __logf(1.0f - pcl));
    float d = gcf - oc;
    float focal = fabsf(gcf - 0.75f) * (d * d);

    AnchorState s;
    s.brx  = br1x;  s.bry  = br1y;
    s.ntlx = -tl1x; s.ntly = -tl1y;
    s.giou = gcf * (2.0f - area2 * (1.0f / (512.0f * 512.0f))) * (1.0f - diou);
    s.fb   = focal * bce;
    s.gcf  = gcf;
    s.thresh = area1 * (2.0f / 3.0f);
    return s;
}

__global__ void __launch_bounds__(128) fused_loss_kernel(
    const float* __restrict__ s_out, const float* __restrict__ m_out,
    const float* __restrict__ l_out,
    const float* __restrict__ s_gt,  const float* __restrict__ m_gt,
    const float* __restrict__ l_gt,
    const float* __restrict__ s_gc,  const float* __restrict__ m_gc,
    const float* __restrict__ l_gc,
    float* __restrict__ out, float inv_b)
{
    __shared__ float4 s_box[NGT_PAD];   // brx, bry, ntlx, ntly  (tl negated)
    __shared__ float  s_th2[NGT_PAD];   // -(area2+eps)*(2/3); sentinel -1e38 on pad
    __shared__ float  s_red[4];

    // ---- map block -> (scale, batch, local block of 256 anchors) ----
    const int bb = blockIdx.x;
    const float *out_t, *gt_t, *gc;
    int b, lb, apb;
    if (bb < 768) {             // s: 48 blocks/batch, 12288 anchors
        b = bb / 48; lb = bb - b * 48; apb = 12288;
        out_t = s_out; gt_t = s_gt; gc = s_gc;
    } else if (bb < 960) {      // m: 12 blocks/batch
        int r = bb - 768; b = r / 12; lb = r - b * 12; apb = 3072;
        out_t = m_out; gt_t = m_gt; gc = m_gc;
    } else {                    // l: 3 blocks/batch
        int r = bb - 960; b = r / 3; lb = r - b * 3; apb = 768;
        out_t = l_out; gt_t = l_gt; gc = l_gc;
    }

    // ---- stage gt boxes (corners with negated tl + scaled threshold) ----
    gc += (size_t)b * NGT * 4;
    for (int n = threadIdx.x; n < NGT_PAD; n += 128) {
        if (n < NGT) {
            float x = gc[n * 4 + 0], y = gc[n * 4 + 1];
            float w = gc[n * 4 + 2], h = gc[n * 4 + 3];
            float hw = 0.5f * w, hh = 0.5f * h;
            s_box[n] = make_float4(x + hw, y + hh, hw - x, hh - y);
            s_th2[n] = -(w * h + EPSF) * (2.0f / 3.0f);
        } else {
            s_box[n] = make_float4(0.0f, 0.0f, 0.0f, 0.0f);
            s_th2[n] = -1.0e38f;    // sentinel: contribution always below threshold
        }
    }
    __syncthreads();

    // ---- two anchors per thread ----
    const int a0 = lb * 256 + threadIdx.x;
    const size_t base0 = ((size_t)b * apb + a0) * 5;
    AnchorState A = prep_anchor(out_t + base0,           gt_t + base0);
    AnchorState C = prep_anchor(out_t + base0 + 128 * 5, gt_t + base0 + 128 * 5);

    // ---- background gate: any(iou vs gt_coords >= 0.5)?
    // iou>=0.5 <=> 3*inter >= a1+a2+eps <=> 2*max(wx,0)*wy >= (2/3)*(a1+a2+eps)
    // 2*max(wx,0) = wx + |wx|  (FADD with free abs modifier -> fma pipe)
    float mA = -3.0e38f, mC = -3.0e38f;
    #pragma unroll 4
    for (int n = 0; n < NGT_PAD; n++) {
        float4 bx = s_box[n];
        float th = s_th2[n];

        float wxA = fminf(A.brx, bx.x) + fminf(A.ntlx, bx.z);
        float wyA = fminf(A.bry, bx.y) + fminf(A.ntly, bx.w);
        float uA  = wxA + fabsf(wxA);                 // 2*max(wxA,0)
        mA = fmaxf(mA, fmaf(uA, wyA, th));

        float wxC = fminf(C.brx, bx.x) + fminf(C.ntlx, bx.z);
        float wyC = fminf(C.bry, bx.y) + fminf(C.ntly, bx.w);
        float uC  = wxC + fabsf(wxC);
        mC = fmaxf(mC, fmaf(uC, wyC, th));
    }

    float bgA = (mA >= A.thresh) ? 0.0f : (1.0f - A.gcf);
    float bgC = (mC >= C.thresh) ? 0.0f : (1.0f - C.gcf);

    float loss = A.giou + A.fb * (A.gcf + bgA)
               + C.giou + C.fb * (C.gcf + bgC);

    // ---- block reduction (4 warps) ----
    #pragma unroll
    for (int off = 16; off > 0; off >>= 1)
        loss += __shfl_down_sync(0xffffffffu, loss, off);

    int wid = threadIdx.x >> 5, lid = threadIdx.x & 31;
    if (lid == 0) s_red[wid] = loss;
    __syncthreads();

    // ---- global accumulate; last block writes output and resets ----
    if (threadIdx.x == 0) {
        float t = s_red[0] + s_red[1] + s_red[2] + s_red[3];
        atomicAdd(&g_acc, (double)t);
        __threadfence();
        unsigned int old = atomicAdd(&g_count, 1u);
        if (old == NBLOCKS - 1) {
            double v = atomicAdd(&g_acc, 0.0);   // coherent read
            out[0] = (float)(v * (double)inv_b);
            g_acc = 0.0;                          // reset for next replay
            g_count = 0u;
            __threadfence();
        }
    }
}

extern "C" void kernel_launch(void* const* d_in, const int* in_sizes, int n_in,
                              void* d_out, int out_size)
{
    const float* s_out = (const float*)d_in[0];
    const float* m_out = (const float*)d_in[1];
    const float* l_out = (const float*)d_in[2];
    const float* s_gt  = (const float*)d_in[3];
    const float* m_gt  = (const float*)d_in[4];
    const float* l_gt  = (const float*)d_in[5];
    const float* s_gc  = (const float*)d_in[6];
    const float* m_gc  = (const float*)d_in[7];
    const float* l_gc  = (const float*)d_in[8];

    const int B = in_sizes[6] / (NGT * 4);   // 16

    fused_loss_kernel<<<NBLOCKS, 128>>>(s_out, m_out, l_out,
                                        s_gt, m_gt, l_gt,
                                        s_gc, m_gc, l_gc,
                                        (float*)d_out, 1.0f / (float)B);
}